// round 14
// baseline (speedup 1.0000x reference)
#include <cuda_runtime.h>
#include <cuda_fp16.h>

typedef unsigned long long ull;

#define N_NODES 100000
#define N_EDGES 1600000
#define F_IN 128
#define H1 64
#define H2 32
#define SCAN_B 391            // ceil(N_NODES/256)

// ---------------- scratch (__device__ globals; no allocation allowed) ------
__device__ __half g_xw1h[(size_t)N_NODES * H1];  // X @ W1 (fp16)
__device__ __half g_h2h[(size_t)N_NODES * H2];   // relu(A@XW1) @ W2 (fp16)
__device__ int    g_deg[N_NODES];
__device__ int    g_off[N_NODES + 1];
__device__ int    g_cur[N_NODES];
__device__ int    g_bsum[512];
__device__ int2   g_edge[N_EDGES];               // (src, w_bits) grouped by dst

// ---------------- f32x2 helpers (Blackwell packed fp32 pipe) ---------------
__device__ __forceinline__ void fma2(ull& d, ull a, ull b) {
    asm("fma.rn.f32x2 %0, %1, %2, %0;" : "+l"(d) : "l"(a), "l"(b));
}
__device__ __forceinline__ ull bcast2(float w) {
    ull r; asm("mov.b64 %0, {%1, %1};" : "=l"(r) : "f"(w)); return r;
}
__device__ __forceinline__ unsigned h2bits(__half2 h) {
    return *reinterpret_cast<unsigned*>(&h);
}

// ---------------- CSR build (round-11 proven: 4 edges/thread) --------------
__global__ __launch_bounds__(256) void count_kernel(const int4* __restrict__ dst4) {
    int q = blockIdx.x * 256 + threadIdx.x;
    if (q * 4 >= N_EDGES) return;
    int4 d = dst4[q];
    atomicAdd(&g_deg[d.x], 1);
    atomicAdd(&g_deg[d.y], 1);
    atomicAdd(&g_deg[d.z], 1);
    atomicAdd(&g_deg[d.w], 1);
}

__global__ __launch_bounds__(256) void scan1_kernel() {
    __shared__ int s[256];
    int t = threadIdx.x;
    int i = blockIdx.x * 256 + t;
    int v = (i < N_NODES) ? g_deg[i] : 0;
    s[t] = v; __syncthreads();
#pragma unroll
    for (int d = 1; d < 256; d <<= 1) {
        int x = (t >= d) ? s[t - d] : 0;
        __syncthreads();
        s[t] += x;
        __syncthreads();
    }
    if (i < N_NODES) g_off[i] = s[t];
    if (t == 255) g_bsum[blockIdx.x] = s[255];
}

__global__ __launch_bounds__(256) void scan3_kernel() {
    __shared__ int s[256];
    int t = threadIdx.x;
    int bid = blockIdx.x;
    int part = 0;
    if (t < bid)       part += g_bsum[t];
    if (t + 256 < bid) part += g_bsum[t + 256];
    s[t] = part; __syncthreads();
#pragma unroll
    for (int d = 128; d > 0; d >>= 1) {
        if (t < d) s[t] += s[t + d];
        __syncthreads();
    }
    int base = s[0];
    int i = bid * 256 + t;
    if (i < N_NODES) {
        int off = g_off[i] - g_deg[i] + base;
        g_off[i] = off;
        g_cur[i] = off;
    }
    if (i == 0) g_off[N_NODES] = N_EDGES;
}

__global__ __launch_bounds__(256) void fill_kernel(const float4* __restrict__ ew4,
                                                   const int4*   __restrict__ src4,
                                                   const int4*   __restrict__ dst4) {
    int q = blockIdx.x * 256 + threadIdx.x;
    if (q * 4 >= N_EDGES) return;
    int4   s = src4[q];
    int4   d = dst4[q];
    float4 w = ew4[q];
    int p0 = atomicAdd(&g_cur[d.x], 1);
    int p1 = atomicAdd(&g_cur[d.y], 1);
    int p2 = atomicAdd(&g_cur[d.z], 1);
    int p3 = atomicAdd(&g_cur[d.w], 1);
    g_edge[p0] = make_int2(s.x, __float_as_int(w.x));
    g_edge[p1] = make_int2(s.y, __float_as_int(w.y));
    g_edge[p2] = make_int2(s.z, __float_as_int(w.z));
    g_edge[p3] = make_int2(s.w, __float_as_int(w.w));
}

// ---------------- GEMM 1: xw1 = X[100k,128] @ W1[128,64] -> fp16 -----------
#define G1_KC 16
#define G1_XP 258
__global__ __launch_bounds__(256) void gemm1_kernel(const float* __restrict__ X,
                                                    const float* __restrict__ W1) {
    __shared__ float sXt[G1_KC * G1_XP];
    __shared__ ull   sW2[G1_KC * H1];
    int tid  = threadIdx.x;
    int row0 = blockIdx.x * 256;
    int tx   = tid & 7;
    int ty   = tid >> 3;

    ull acc[4][8];
#pragma unroll
    for (int p = 0; p < 4; p++)
#pragma unroll
        for (int c = 0; c < 8; c++) acc[p][c] = 0ull;

    for (int kc = 0; kc < F_IN; kc += G1_KC) {
#pragma unroll
        for (int j = 0; j < 4; j++) {
            int i = tid + j * 256;
            int r = i >> 2, kq = i & 3;
            int row = row0 + r;
            float4 v = make_float4(0.f, 0.f, 0.f, 0.f);
            if (row < N_NODES)
                v = *reinterpret_cast<const float4*>(&X[(size_t)row * F_IN + kc + kq * 4]);
            sXt[(kq * 4 + 0) * G1_XP + r] = v.x;
            sXt[(kq * 4 + 1) * G1_XP + r] = v.y;
            sXt[(kq * 4 + 2) * G1_XP + r] = v.z;
            sXt[(kq * 4 + 3) * G1_XP + r] = v.w;
        }
#pragma unroll
        for (int j = 0; j < 4; j++) {
            int i = tid + j * 256;
            int k = i >> 6, c = i & 63;
            sW2[k * H1 + c] = bcast2(W1[(size_t)(kc + k) * H1 + c]);
        }
        __syncthreads();
#pragma unroll
        for (int k = 0; k < G1_KC; k++) {
            const ull* xk = reinterpret_cast<const ull*>(&sXt[k * G1_XP + ty * 8]);
            ull x0 = xk[0], x1 = xk[1], x2 = xk[2], x3 = xk[3];
            const ull* wk = &sW2[k * H1 + tx * 8];
#pragma unroll
            for (int c = 0; c < 8; c++) {
                ull wb = wk[c];
                fma2(acc[0][c], x0, wb);
                fma2(acc[1][c], x1, wb);
                fma2(acc[2][c], x2, wb);
                fma2(acc[3][c], x3, wb);
            }
        }
        __syncthreads();
    }
#pragma unroll
    for (int p = 0; p < 4; p++) {
#pragma unroll
        for (int h = 0; h < 2; h++) {
            int row = row0 + ty * 8 + 2 * p + h;
            if (row < N_NODES) {
                float o[8];
#pragma unroll
                for (int c = 0; c < 8; c++) {
                    unsigned v = h ? (unsigned)(acc[p][c] >> 32) : (unsigned)acc[p][c];
                    o[c] = __uint_as_float(v);
                }
                uint4 st;
                st.x = h2bits(__floats2half2_rn(o[0], o[1]));
                st.y = h2bits(__floats2half2_rn(o[2], o[3]));
                st.z = h2bits(__floats2half2_rn(o[4], o[5]));
                st.w = h2bits(__floats2half2_rn(o[6], o[7]));
                *reinterpret_cast<uint4*>(&g_xw1h[(size_t)row * H1 + tx * 8]) = st;
            }
        }
    }
}

// ------ fused aggregation 1 + GEMM 2: h2 = relu(A @ xw1) @ W2 -> fp16 ------
// warp per dst node; edge loop as round-11; epilogue: a1 row to smem, then
// per-lane 64-step matvec against W2 (smem). g_a1 global array eliminated.
__global__ __launch_bounds__(256) void agg1_kernel(const float* __restrict__ W2) {
    __shared__ float sW[H1 * H2];        // 8 KB  [k][c]
    __shared__ float sA[8][H1];          // 2 KB  per-warp a1 row
    int tid = threadIdx.x;
#pragma unroll
    for (int j = 0; j < 8; j++)
        sW[tid + j * 256] = W2[tid + j * 256];
    __syncthreads();

    int w    = tid >> 5;
    int lane = tid & 31;
    int node = blockIdx.x * 8 + w;
    if (node >= N_NODES) return;

    int p = g_off[node], e = g_off[node + 1];
    float2 a0 = make_float2(0.f, 0.f), a1v = make_float2(0.f, 0.f);
    const __half2* base = reinterpret_cast<const __half2*>(g_xw1h) + lane;
    for (; p + 8 <= e; p += 8) {
        int2 r0 = g_edge[p + 0];
        int2 r1 = g_edge[p + 1];
        int2 r2 = g_edge[p + 2];
        int2 r3 = g_edge[p + 3];
        int2 r4 = g_edge[p + 4];
        int2 r5 = g_edge[p + 5];
        int2 r6 = g_edge[p + 6];
        int2 r7 = g_edge[p + 7];
        float2 v0 = __half22float2(base[(size_t)r0.x * (H1 / 2)]);
        float2 v1 = __half22float2(base[(size_t)r1.x * (H1 / 2)]);
        float2 v2 = __half22float2(base[(size_t)r2.x * (H1 / 2)]);
        float2 v3 = __half22float2(base[(size_t)r3.x * (H1 / 2)]);
        float2 v4 = __half22float2(base[(size_t)r4.x * (H1 / 2)]);
        float2 v5 = __half22float2(base[(size_t)r5.x * (H1 / 2)]);
        float2 v6 = __half22float2(base[(size_t)r6.x * (H1 / 2)]);
        float2 v7 = __half22float2(base[(size_t)r7.x * (H1 / 2)]);
        float w0 = __int_as_float(r0.y), w1 = __int_as_float(r1.y);
        float w2 = __int_as_float(r2.y), w3 = __int_as_float(r3.y);
        float w4 = __int_as_float(r4.y), w5 = __int_as_float(r5.y);
        float w6 = __int_as_float(r6.y), w7 = __int_as_float(r7.y);
        a0.x  = fmaf(w0, v0.x, a0.x);  a0.y  = fmaf(w0, v0.y, a0.y);
        a1v.x = fmaf(w1, v1.x, a1v.x); a1v.y = fmaf(w1, v1.y, a1v.y);
        a0.x  = fmaf(w2, v2.x, a0.x);  a0.y  = fmaf(w2, v2.y, a0.y);
        a1v.x = fmaf(w3, v3.x, a1v.x); a1v.y = fmaf(w3, v3.y, a1v.y);
        a0.x  = fmaf(w4, v4.x, a0.x);  a0.y  = fmaf(w4, v4.y, a0.y);
        a1v.x = fmaf(w5, v5.x, a1v.x); a1v.y = fmaf(w5, v5.y, a1v.y);
        a0.x  = fmaf(w6, v6.x, a0.x);  a0.y  = fmaf(w6, v6.y, a0.y);
        a1v.x = fmaf(w7, v7.x, a1v.x); a1v.y = fmaf(w7, v7.y, a1v.y);
    }
    for (; p < e; p++) {
        int2 r = g_edge[p];
        float wv = __int_as_float(r.y);
        float2 v = __half22float2(base[(size_t)r.x * (H1 / 2)]);
        a0.x = fmaf(wv, v.x, a0.x);
        a0.y = fmaf(wv, v.y, a0.y);
    }
    // relu + stash a1 row in smem (this warp only -> __syncwarp suffices)
    sA[w][lane * 2 + 0] = fmaxf(a0.x + a1v.x, 0.f);
    sA[w][lane * 2 + 1] = fmaxf(a0.y + a1v.y, 0.f);
    __syncwarp();

    // per-lane matvec: h2[lane] = sum_k a1[k] * W2[k][lane]
    const float* a = sA[w];
    float h0 = 0.f, h1 = 0.f;
#pragma unroll
    for (int k = 0; k < H1; k += 2) {
        h0 = fmaf(a[k + 0], sW[(k + 0) * H2 + lane], h0);
        h1 = fmaf(a[k + 1], sW[(k + 1) * H2 + lane], h1);
    }
    g_h2h[(size_t)node * H2 + lane] = __float2half(h0 + h1);
}

// ---------------- aggregation 2: out = sum_e w*h2[src] ---------------------
__global__ __launch_bounds__(256) void agg2_kernel(float* __restrict__ out) {
    int node = blockIdx.x * 8 + (threadIdx.x >> 5);
    if (node >= N_NODES) return;
    int lane = threadIdx.x & 31;
    int p = g_off[node], e = g_off[node + 1];
    float a0 = 0.f, a1v = 0.f;
    const __half* base = g_h2h + lane;
    for (; p + 8 <= e; p += 8) {
        int2 r0 = g_edge[p + 0];
        int2 r1 = g_edge[p + 1];
        int2 r2 = g_edge[p + 2];
        int2 r3 = g_edge[p + 3];
        int2 r4 = g_edge[p + 4];
        int2 r5 = g_edge[p + 5];
        int2 r6 = g_edge[p + 6];
        int2 r7 = g_edge[p + 7];
        float v0 = __half2float(base[(size_t)r0.x * H2]);
        float v1 = __half2float(base[(size_t)r1.x * H2]);
        float v2 = __half2float(base[(size_t)r2.x * H2]);
        float v3 = __half2float(base[(size_t)r3.x * H2]);
        float v4 = __half2float(base[(size_t)r4.x * H2]);
        float v5 = __half2float(base[(size_t)r5.x * H2]);
        float v6 = __half2float(base[(size_t)r6.x * H2]);
        float v7 = __half2float(base[(size_t)r7.x * H2]);
        a0  = fmaf(__int_as_float(r0.y), v0, a0);
        a1v = fmaf(__int_as_float(r1.y), v1, a1v);
        a0  = fmaf(__int_as_float(r2.y), v2, a0);
        a1v = fmaf(__int_as_float(r3.y), v3, a1v);
        a0  = fmaf(__int_as_float(r4.y), v4, a0);
        a1v = fmaf(__int_as_float(r5.y), v5, a1v);
        a0  = fmaf(__int_as_float(r6.y), v6, a0);
        a1v = fmaf(__int_as_float(r7.y), v7, a1v);
    }
    for (; p < e; p++) {
        int2 r = g_edge[p];
        a0 = fmaf(__int_as_float(r.y), __half2float(base[(size_t)r.x * H2]), a0);
    }
    out[(size_t)node * H2 + lane] = a0 + a1v;
}

// ---------------- launch: round-11 structure, gemm2 fused away -------------
extern "C" void kernel_launch(void* const* d_in, const int* in_sizes, int n_in,
                              void* d_out, int out_size) {
    const float* features = (const float*)d_in[0];
    const float* ew       = (const float*)d_in[1];
    const float* W1       = (const float*)d_in[2];
    const float* W2       = (const float*)d_in[3];
    const int*   src      = (const int*)d_in[4];
    const int*   dst      = (const int*)d_in[5];
    float*       out      = (float*)d_out;

    cudaStream_t s2 = 0;
    cudaEvent_t  e0 = 0, e1 = 0;
    bool fork =
        (cudaStreamCreateWithFlags(&s2, cudaStreamNonBlocking) == cudaSuccess) &&
        (cudaEventCreateWithFlags(&e0, cudaEventDisableTiming) == cudaSuccess) &&
        (cudaEventCreateWithFlags(&e1, cudaEventDisableTiming) == cudaSuccess);
    cudaStream_t sb = fork ? s2 : (cudaStream_t)0;

    if (fork) {
        cudaEventRecord(e0, 0);
        cudaStreamWaitEvent(s2, e0, 0);
    }

    // --- build chain on side stream (round-11 proven) ---
    void* degPtr = nullptr;
    cudaGetSymbolAddress(&degPtr, g_deg);
    cudaMemsetAsync(degPtr, 0, N_NODES * sizeof(int), sb);
    count_kernel<<<(N_EDGES / 4 + 255) / 256, 256, 0, sb>>>((const int4*)dst);
    scan1_kernel<<<SCAN_B, 256, 0, sb>>>();
    scan3_kernel<<<SCAN_B, 256, 0, sb>>>();
    fill_kernel<<<(N_EDGES / 4 + 255) / 256, 256, 0, sb>>>(
        (const float4*)ew, (const int4*)src, (const int4*)dst);

    // --- gemm1 concurrently on main stream ---
    gemm1_kernel<<<(N_NODES + 255) / 256, 256>>>(features, W1);

    if (fork) {
        cudaEventRecord(e1, s2);
        cudaStreamWaitEvent(0, e1, 0);
    }

    agg1_kernel<<<(N_NODES + 7) / 8, 256>>>(W2);
    agg2_kernel<<<(N_NODES + 7) / 8, 256>>>(out);
}

// round 17
// speedup vs baseline: 1.0429x; 1.0429x over previous
#include <cuda_runtime.h>
#include <cuda_fp16.h>

typedef unsigned long long ull;

#define N_NODES 100000
#define N_EDGES 1600000
#define F_IN 128
#define H1 64
#define H2 32
#define SCAN_B 391            // ceil(N_NODES/256)

// ---------------- scratch (__device__ globals; no allocation allowed) ------
__device__ __half g_xw1h[(size_t)N_NODES * H1];  // X @ W1 (fp16)
__device__ __half g_a1h [(size_t)N_NODES * H1];  // relu(A @ XW1) (fp16)
__device__ __half g_h2h [(size_t)N_NODES * H2];  // a1 @ W2 (fp16)
__device__ int    g_deg[N_NODES];
__device__ int    g_off[N_NODES + 1];
__device__ int    g_cur[N_NODES];
__device__ int    g_bsum[512];
__device__ int2   g_edge[N_EDGES];               // (src, w_bits) grouped by dst

// ---------------- f32x2 helpers (Blackwell packed fp32 pipe) ---------------
__device__ __forceinline__ void fma2(ull& d, ull a, ull b) {
    asm("fma.rn.f32x2 %0, %1, %2, %0;" : "+l"(d) : "l"(a), "l"(b));
}
__device__ __forceinline__ ull bcast2(float w) {
    ull r; asm("mov.b64 %0, {%1, %1};" : "=l"(r) : "f"(w)); return r;
}
__device__ __forceinline__ unsigned h2bits(__half2 h) {
    return *reinterpret_cast<unsigned*>(&h);
}
__device__ __forceinline__ float2 u2f2(unsigned u) {
    __half2 h = *reinterpret_cast<__half2*>(&u);
    return __half22float2(h);
}

// ---------------- CSR build (round-11 proven: 4 edges/thread) --------------
__global__ __launch_bounds__(256) void count_kernel(const int4* __restrict__ dst4) {
    int q = blockIdx.x * 256 + threadIdx.x;
    if (q * 4 >= N_EDGES) return;
    int4 d = dst4[q];
    atomicAdd(&g_deg[d.x], 1);
    atomicAdd(&g_deg[d.y], 1);
    atomicAdd(&g_deg[d.z], 1);
    atomicAdd(&g_deg[d.w], 1);
}

__global__ __launch_bounds__(256) void scan1_kernel() {
    __shared__ int s[256];
    int t = threadIdx.x;
    int i = blockIdx.x * 256 + t;
    int v = (i < N_NODES) ? g_deg[i] : 0;
    s[t] = v; __syncthreads();
#pragma unroll
    for (int d = 1; d < 256; d <<= 1) {
        int x = (t >= d) ? s[t - d] : 0;
        __syncthreads();
        s[t] += x;
        __syncthreads();
    }
    if (i < N_NODES) g_off[i] = s[t];
    if (t == 255) g_bsum[blockIdx.x] = s[255];
}

__global__ __launch_bounds__(256) void scan3_kernel() {
    __shared__ int s[256];
    int t = threadIdx.x;
    int bid = blockIdx.x;
    int part = 0;
    if (t < bid)       part += g_bsum[t];
    if (t + 256 < bid) part += g_bsum[t + 256];
    s[t] = part; __syncthreads();
#pragma unroll
    for (int d = 128; d > 0; d >>= 1) {
        if (t < d) s[t] += s[t + d];
        __syncthreads();
    }
    int base = s[0];
    int i = bid * 256 + t;
    if (i < N_NODES) {
        int off = g_off[i] - g_deg[i] + base;
        g_off[i] = off;
        g_cur[i] = off;
    }
    if (i == 0) g_off[N_NODES] = N_EDGES;
}

__global__ __launch_bounds__(256) void fill_kernel(const float4* __restrict__ ew4,
                                                   const int4*   __restrict__ src4,
                                                   const int4*   __restrict__ dst4) {
    int q = blockIdx.x * 256 + threadIdx.x;
    if (q * 4 >= N_EDGES) return;
    int4   s = src4[q];
    int4   d = dst4[q];
    float4 w = ew4[q];
    int p0 = atomicAdd(&g_cur[d.x], 1);
    int p1 = atomicAdd(&g_cur[d.y], 1);
    int p2 = atomicAdd(&g_cur[d.z], 1);
    int p3 = atomicAdd(&g_cur[d.w], 1);
    g_edge[p0] = make_int2(s.x, __float_as_int(w.x));
    g_edge[p1] = make_int2(s.y, __float_as_int(w.y));
    g_edge[p2] = make_int2(s.z, __float_as_int(w.z));
    g_edge[p3] = make_int2(s.w, __float_as_int(w.w));
}

// ---------------- GEMM 1: xw1 = X[100k,128] @ W1[128,64] -> fp16 -----------
#define G1_KC 16
#define G1_XP 258
__global__ __launch_bounds__(256) void gemm1_kernel(const float* __restrict__ X,
                                                    const float* __restrict__ W1) {
    __shared__ float sXt[G1_KC * G1_XP];
    __shared__ ull   sW2[G1_KC * H1];
    int tid  = threadIdx.x;
    int row0 = blockIdx.x * 256;
    int tx   = tid & 7;
    int ty   = tid >> 3;

    ull acc[4][8];
#pragma unroll
    for (int p = 0; p < 4; p++)
#pragma unroll
        for (int c = 0; c < 8; c++) acc[p][c] = 0ull;

    for (int kc = 0; kc < F_IN; kc += G1_KC) {
#pragma unroll
        for (int j = 0; j < 4; j++) {
            int i = tid + j * 256;
            int r = i >> 2, kq = i & 3;
            int row = row0 + r;
            float4 v = make_float4(0.f, 0.f, 0.f, 0.f);
            if (row < N_NODES)
                v = *reinterpret_cast<const float4*>(&X[(size_t)row * F_IN + kc + kq * 4]);
            sXt[(kq * 4 + 0) * G1_XP + r] = v.x;
            sXt[(kq * 4 + 1) * G1_XP + r] = v.y;
            sXt[(kq * 4 + 2) * G1_XP + r] = v.z;
            sXt[(kq * 4 + 3) * G1_XP + r] = v.w;
        }
#pragma unroll
        for (int j = 0; j < 4; j++) {
            int i = tid + j * 256;
            int k = i >> 6, c = i & 63;
            sW2[k * H1 + c] = bcast2(W1[(size_t)(kc + k) * H1 + c]);
        }
        __syncthreads();
#pragma unroll
        for (int k = 0; k < G1_KC; k++) {
            const ull* xk = reinterpret_cast<const ull*>(&sXt[k * G1_XP + ty * 8]);
            ull x0 = xk[0], x1 = xk[1], x2 = xk[2], x3 = xk[3];
            const ull* wk = &sW2[k * H1 + tx * 8];
#pragma unroll
            for (int c = 0; c < 8; c++) {
                ull wb = wk[c];
                fma2(acc[0][c], x0, wb);
                fma2(acc[1][c], x1, wb);
                fma2(acc[2][c], x2, wb);
                fma2(acc[3][c], x3, wb);
            }
        }
        __syncthreads();
    }
#pragma unroll
    for (int p = 0; p < 4; p++) {
#pragma unroll
        for (int h = 0; h < 2; h++) {
            int row = row0 + ty * 8 + 2 * p + h;
            if (row < N_NODES) {
                float o[8];
#pragma unroll
                for (int c = 0; c < 8; c++) {
                    unsigned v = h ? (unsigned)(acc[p][c] >> 32) : (unsigned)acc[p][c];
                    o[c] = __uint_as_float(v);
                }
                uint4 st;
                st.x = h2bits(__floats2half2_rn(o[0], o[1]));
                st.y = h2bits(__floats2half2_rn(o[2], o[3]));
                st.z = h2bits(__floats2half2_rn(o[4], o[5]));
                st.w = h2bits(__floats2half2_rn(o[6], o[7]));
                *reinterpret_cast<uint4*>(&g_xw1h[(size_t)row * H1 + tx * 8]) = st;
            }
        }
    }
}

// ---------------- aggregation 1: a1 = relu(sum_e w*xw1[src]) -> fp16 -------
__global__ __launch_bounds__(256) void agg1_kernel() {
    int node = blockIdx.x * 8 + (threadIdx.x >> 5);
    if (node >= N_NODES) return;
    int lane = threadIdx.x & 31;
    int p = g_off[node], e = g_off[node + 1];
    float2 a0 = make_float2(0.f, 0.f), a1v = make_float2(0.f, 0.f);
    const __half2* base = reinterpret_cast<const __half2*>(g_xw1h) + lane;
    for (; p + 8 <= e; p += 8) {
        int2 r0 = g_edge[p + 0];
        int2 r1 = g_edge[p + 1];
        int2 r2 = g_edge[p + 2];
        int2 r3 = g_edge[p + 3];
        int2 r4 = g_edge[p + 4];
        int2 r5 = g_edge[p + 5];
        int2 r6 = g_edge[p + 6];
        int2 r7 = g_edge[p + 7];
        float2 v0 = __half22float2(base[(size_t)r0.x * (H1 / 2)]);
        float2 v1 = __half22float2(base[(size_t)r1.x * (H1 / 2)]);
        float2 v2 = __half22float2(base[(size_t)r2.x * (H1 / 2)]);
        float2 v3 = __half22float2(base[(size_t)r3.x * (H1 / 2)]);
        float2 v4 = __half22float2(base[(size_t)r4.x * (H1 / 2)]);
        float2 v5 = __half22float2(base[(size_t)r5.x * (H1 / 2)]);
        float2 v6 = __half22float2(base[(size_t)r6.x * (H1 / 2)]);
        float2 v7 = __half22float2(base[(size_t)r7.x * (H1 / 2)]);
        float w0 = __int_as_float(r0.y), w1 = __int_as_float(r1.y);
        float w2 = __int_as_float(r2.y), w3 = __int_as_float(r3.y);
        float w4 = __int_as_float(r4.y), w5 = __int_as_float(r5.y);
        float w6 = __int_as_float(r6.y), w7 = __int_as_float(r7.y);
        a0.x  = fmaf(w0, v0.x, a0.x);  a0.y  = fmaf(w0, v0.y, a0.y);
        a1v.x = fmaf(w1, v1.x, a1v.x); a1v.y = fmaf(w1, v1.y, a1v.y);
        a0.x  = fmaf(w2, v2.x, a0.x);  a0.y  = fmaf(w2, v2.y, a0.y);
        a1v.x = fmaf(w3, v3.x, a1v.x); a1v.y = fmaf(w3, v3.y, a1v.y);
        a0.x  = fmaf(w4, v4.x, a0.x);  a0.y  = fmaf(w4, v4.y, a0.y);
        a1v.x = fmaf(w5, v5.x, a1v.x); a1v.y = fmaf(w5, v5.y, a1v.y);
        a0.x  = fmaf(w6, v6.x, a0.x);  a0.y  = fmaf(w6, v6.y, a0.y);
        a1v.x = fmaf(w7, v7.x, a1v.x); a1v.y = fmaf(w7, v7.y, a1v.y);
    }
    for (; p < e; p++) {
        int2 r = g_edge[p];
        float w = __int_as_float(r.y);
        float2 v = __half22float2(base[(size_t)r.x * (H1 / 2)]);
        a0.x = fmaf(w, v.x, a0.x);
        a0.y = fmaf(w, v.y, a0.y);
    }
    __half2 hv = __floats2half2_rn(fmaxf(a0.x + a1v.x, 0.f),
                                   fmaxf(a0.y + a1v.y, 0.f));
    reinterpret_cast<__half2*>(g_a1h)[(size_t)node * (H1 / 2) + lane] = hv;
}

// ---------------- GEMM 2: h2 = a1h[100k,64] @ W2[64,32] -> fp16 ------------
// round-8 tile (128 thr, 256 rows x 32 cols, 8x8), staging reads fp16 a1.
#define G2_KC 16
__global__ __launch_bounds__(128) void gemm2_kernel(const float* __restrict__ W2) {
    __shared__ float sXt[G2_KC * G1_XP];
    __shared__ ull   sW2[G2_KC * H2];
    int tid  = threadIdx.x;
    int row0 = blockIdx.x * 256;
    int tx   = tid & 3;
    int ty   = tid >> 2;

    ull acc[4][8];
#pragma unroll
    for (int p = 0; p < 4; p++)
#pragma unroll
        for (int c = 0; c < 8; c++) acc[p][c] = 0ull;

    for (int kc = 0; kc < H1; kc += G2_KC) {
        // stage 256 rows x 16 k of fp16 a1: uint4 = 8 halves per load
#pragma unroll
        for (int j = 0; j < 4; j++) {
            int i = tid + j * 128;            // 0..511
            int r = i >> 1, kq = i & 1;       // row, half-of-16
            int row = row0 + r;
            uint4 v = make_uint4(0u, 0u, 0u, 0u);
            if (row < N_NODES)
                v = *reinterpret_cast<const uint4*>(&g_a1h[(size_t)row * H1 + kc + kq * 8]);
            float2 f0 = u2f2(v.x), f1 = u2f2(v.y), f2 = u2f2(v.z), f3 = u2f2(v.w);
            int kb = kq * 8;
            sXt[(kb + 0) * G1_XP + r] = f0.x;
            sXt[(kb + 1) * G1_XP + r] = f0.y;
            sXt[(kb + 2) * G1_XP + r] = f1.x;
            sXt[(kb + 3) * G1_XP + r] = f1.y;
            sXt[(kb + 4) * G1_XP + r] = f2.x;
            sXt[(kb + 5) * G1_XP + r] = f2.y;
            sXt[(kb + 6) * G1_XP + r] = f3.x;
            sXt[(kb + 7) * G1_XP + r] = f3.y;
        }
#pragma unroll
        for (int j = 0; j < 4; j++) {
            int i = tid + j * 128;
            int k = i >> 5, c = i & 31;
            sW2[k * H2 + c] = bcast2(W2[(size_t)(kc + k) * H2 + c]);
        }
        __syncthreads();
#pragma unroll
        for (int k = 0; k < G2_KC; k++) {
            const ull* xk = reinterpret_cast<const ull*>(&sXt[k * G1_XP + ty * 8]);
            ull x0 = xk[0], x1 = xk[1], x2 = xk[2], x3 = xk[3];
            const ull* wk = &sW2[k * H2 + tx * 8];
#pragma unroll
            for (int c = 0; c < 8; c++) {
                ull wb = wk[c];
                fma2(acc[0][c], x0, wb);
                fma2(acc[1][c], x1, wb);
                fma2(acc[2][c], x2, wb);
                fma2(acc[3][c], x3, wb);
            }
        }
        __syncthreads();
    }
#pragma unroll
    for (int p = 0; p < 4; p++) {
#pragma unroll
        for (int h = 0; h < 2; h++) {
            int row = row0 + ty * 8 + 2 * p + h;
            if (row < N_NODES) {
                float o[8];
#pragma unroll
                for (int c = 0; c < 8; c++) {
                    unsigned v = h ? (unsigned)(acc[p][c] >> 32) : (unsigned)acc[p][c];
                    o[c] = __uint_as_float(v);
                }
                uint4 st;
                st.x = h2bits(__floats2half2_rn(o[0], o[1]));
                st.y = h2bits(__floats2half2_rn(o[2], o[3]));
                st.z = h2bits(__floats2half2_rn(o[4], o[5]));
                st.w = h2bits(__floats2half2_rn(o[6], o[7]));
                *reinterpret_cast<uint4*>(&g_h2h[(size_t)row * H2 + tx * 8]) = st;
            }
        }
    }
}

// ---------------- aggregation 2: out = sum_e w*h2[src] ---------------------
__global__ __launch_bounds__(256) void agg2_kernel(float* __restrict__ out) {
    int node = blockIdx.x * 8 + (threadIdx.x >> 5);
    if (node >= N_NODES) return;
    int lane = threadIdx.x & 31;
    int p = g_off[node], e = g_off[node + 1];
    float a0 = 0.f, a1v = 0.f;
    const __half* base = g_h2h + lane;
    for (; p + 8 <= e; p += 8) {
        int2 r0 = g_edge[p + 0];
        int2 r1 = g_edge[p + 1];
        int2 r2 = g_edge[p + 2];
        int2 r3 = g_edge[p + 3];
        int2 r4 = g_edge[p + 4];
        int2 r5 = g_edge[p + 5];
        int2 r6 = g_edge[p + 6];
        int2 r7 = g_edge[p + 7];
        float v0 = __half2float(base[(size_t)r0.x * H2]);
        float v1 = __half2float(base[(size_t)r1.x * H2]);
        float v2 = __half2float(base[(size_t)r2.x * H2]);
        float v3 = __half2float(base[(size_t)r3.x * H2]);
        float v4 = __half2float(base[(size_t)r4.x * H2]);
        float v5 = __half2float(base[(size_t)r5.x * H2]);
        float v6 = __half2float(base[(size_t)r6.x * H2]);
        float v7 = __half2float(base[(size_t)r7.x * H2]);
        a0  = fmaf(__int_as_float(r0.y), v0, a0);
        a1v = fmaf(__int_as_float(r1.y), v1, a1v);
        a0  = fmaf(__int_as_float(r2.y), v2, a0);
        a1v = fmaf(__int_as_float(r3.y), v3, a1v);
        a0  = fmaf(__int_as_float(r4.y), v4, a0);
        a1v = fmaf(__int_as_float(r5.y), v5, a1v);
        a0  = fmaf(__int_as_float(r6.y), v6, a0);
        a1v = fmaf(__int_as_float(r7.y), v7, a1v);
    }
    for (; p < e; p++) {
        int2 r = g_edge[p];
        a0 = fmaf(__int_as_float(r.y), __half2float(base[(size_t)r.x * H2]), a0);
    }
    out[(size_t)node * H2 + lane] = a0 + a1v;
}

// ---------------- launch: round-11 structure (proven) ----------------------
extern "C" void kernel_launch(void* const* d_in, const int* in_sizes, int n_in,
                              void* d_out, int out_size) {
    const float* features = (const float*)d_in[0];
    const float* ew       = (const float*)d_in[1];
    const float* W1       = (const float*)d_in[2];
    const float* W2       = (const float*)d_in[3];
    const int*   src      = (const int*)d_in[4];
    const int*   dst      = (const int*)d_in[5];
    float*       out      = (float*)d_out;

    cudaStream_t s2 = 0;
    cudaEvent_t  e0 = 0, e1 = 0;
    bool fork =
        (cudaStreamCreateWithFlags(&s2, cudaStreamNonBlocking) == cudaSuccess) &&
        (cudaEventCreateWithFlags(&e0, cudaEventDisableTiming) == cudaSuccess) &&
        (cudaEventCreateWithFlags(&e1, cudaEventDisableTiming) == cudaSuccess);
    cudaStream_t sb = fork ? s2 : (cudaStream_t)0;

    if (fork) {
        cudaEventRecord(e0, 0);
        cudaStreamWaitEvent(s2, e0, 0);
    }

    // --- build chain on side stream ---
    void* degPtr = nullptr;
    cudaGetSymbolAddress(&degPtr, g_deg);
    cudaMemsetAsync(degPtr, 0, N_NODES * sizeof(int), sb);
    count_kernel<<<(N_EDGES / 4 + 255) / 256, 256, 0, sb>>>((const int4*)dst);
    scan1_kernel<<<SCAN_B, 256, 0, sb>>>();
    scan3_kernel<<<SCAN_B, 256, 0, sb>>>();
    fill_kernel<<<(N_EDGES / 4 + 255) / 256, 256, 0, sb>>>(
        (const float4*)ew, (const int4*)src, (const int4*)dst);

    // --- gemm1 concurrently on main stream ---
    gemm1_kernel<<<(N_NODES + 255) / 256, 256>>>(features, W1);

    if (fork) {
        cudaEventRecord(e1, s2);
        cudaStreamWaitEvent(0, e1, 0);
    }

    agg1_kernel<<<(N_NODES + 7) / 8, 256>>>();
    gemm2_kernel<<<(N_NODES + 255) / 256, 128>>>(W2);
    agg2_kernel<<<(N_NODES + 7) / 8, 256>>>(out);
}